// round 8
// baseline (speedup 1.0000x reference)
#include <cuda_runtime.h>
#include <cstdint>

// GradientAwareAreaUtil: per-image  sum(Y) - 0.1*(sum|vdiff| + sum|hdiff|)
// B=512, 256x256 fp32. cp.async.bulk (UBLKCP) + mbarrier staging pipeline:
// loads decoupled from warps -> ~128KB in flight per SM.

#define H 256
#define W 256
#define BATCH 512
#define PENALTY 0.1f

#define STAGE_ROWS 8
#define NSTAGES 16                    // per half-image (128 rows)
#define RING 3
#define STAGE_FLOATS (STAGE_ROWS * W) // 2048
#define STAGE_BYTES  (STAGE_FLOATS * 4)

struct SmemLayout {
    float buf[RING][STAGE_FLOATS];    // 24 KB
    float extra[W];                   // 1 KB (row 128 for half 0)
    unsigned long long full_bar[RING];
    unsigned long long empty_bar[RING];
    float s_area[4];
    float s_grad[4];
};

__device__ __forceinline__ unsigned sm_addr(const void* p) {
    return (unsigned)__cvta_generic_to_shared(p);
}

__device__ __forceinline__ void mbar_init(unsigned bar, unsigned count) {
    asm volatile("mbarrier.init.shared.b64 [%0], %1;" :: "r"(bar), "r"(count) : "memory");
}
__device__ __forceinline__ void mbar_expect_tx(unsigned bar, unsigned bytes) {
    asm volatile("mbarrier.arrive.expect_tx.shared.b64 _, [%0], %1;"
                 :: "r"(bar), "r"(bytes) : "memory");
}
__device__ __forceinline__ void mbar_arrive(unsigned bar) {
    asm volatile("mbarrier.arrive.shared.b64 _, [%0];" :: "r"(bar) : "memory");
}
__device__ __forceinline__ void mbar_wait(unsigned bar, unsigned parity) {
    asm volatile(
        "{\n\t.reg .pred p;\n\t"
        "WL_%=:\n\t"
        "mbarrier.try_wait.parity.acquire.cta.shared::cta.b64 p, [%0], %1, 0x989680;\n\t"
        "@!p bra WL_%=;\n\t}"
        :: "r"(bar), "r"(parity) : "memory");
}
__device__ __forceinline__ void bulk_g2s(unsigned dst, const void* src,
                                         unsigned bytes, unsigned bar) {
    asm volatile(
        "cp.async.bulk.shared::cluster.global.mbarrier::complete_tx::bytes "
        "[%0], [%1], %2, [%3];"
        :: "r"(dst), "l"(src), "r"(bytes), "r"(bar) : "memory");
}

__device__ __forceinline__ float sum8(const float4& a, const float4& b) {
    return ((a.x + a.y) + (a.z + a.w)) + ((b.x + b.y) + (b.z + b.w));
}
__device__ __forceinline__ float vdiff8(const float4& a0, const float4& a1,
                                        const float4& b0, const float4& b1) {
    return fabsf(a0.x - b0.x) + fabsf(a0.y - b0.y) + fabsf(a0.z - b0.z) + fabsf(a0.w - b0.w)
         + fabsf(a1.x - b1.x) + fabsf(a1.y - b1.y) + fabsf(a1.z - b1.z) + fabsf(a1.w - b1.w);
}
__device__ __forceinline__ float hdiff7(const float4& a0, const float4& a1) {
    return fabsf(a0.x - a0.y) + fabsf(a0.y - a0.z) + fabsf(a0.z - a0.w)
         + fabsf(a0.w - a1.x)
         + fabsf(a1.x - a1.y) + fabsf(a1.y - a1.z) + fabsf(a1.z - a1.w);
}

__global__ void __launch_bounds__(128, 8)
grad_area_kernel(const float* __restrict__ Y, float* __restrict__ out)
{
    __shared__ SmemLayout smem;

    const int cta  = blockIdx.x;      // 0..1023
    const int b    = cta >> 1;
    const int half = cta & 1;
    const int tid  = threadIdx.x;
    const int warp = tid >> 5;
    const int lane = tid & 31;

    const float* src_base = Y + (size_t)b * (H * W) + (size_t)half * 128 * W;

    if (tid == 0) {
        #pragma unroll
        for (int j = 0; j < RING; ++j) {
            mbar_init(sm_addr(&smem.full_bar[j]), 1);
            mbar_init(sm_addr(&smem.empty_bar[j]), 128);
        }
        asm volatile("fence.proxy.async.shared::cta;" ::: "memory");
    }
    __syncthreads();

    // Prologue: issue stages 0..RING-1
    if (tid == 0) {
        #pragma unroll
        for (int s = 0; s < RING; ++s) {
            unsigned fb = sm_addr(&smem.full_bar[s]);
            mbar_expect_tx(fb, STAGE_BYTES);
            bulk_g2s(sm_addr(smem.buf[s]), src_base + s * STAGE_FLOATS,
                     STAGE_BYTES, fb);
        }
    }

    float area = 0.0f, grad = 0.0f;
    float4 P0, P1;                    // warp 3: previous stage's row 7
    P0 = make_float4(0, 0, 0, 0); P1 = P0;

    const int r0  = 2 * warp;         // rows within stage
    const int col = 8 * lane;

    for (int s = 0; s < NSTAGES; ++s) {
        const int bufi = s % RING;
        mbar_wait(sm_addr(&smem.full_bar[bufi]), (unsigned)((s / RING) & 1));

        const float* Bp = smem.buf[bufi];

        // Deferred vdiff: prev stage row 7 vs this stage row 0 (warp 3)
        if (warp == 3 && s > 0) {
            const float4* rn = (const float4*)(Bp + col);
            grad += vdiff8(P0, P1, rn[0], rn[1]);
        }

        const float4* pA = (const float4*)(Bp + r0 * W + col);
        const float4* pB = (const float4*)(Bp + (r0 + 1) * W + col);
        float4 A0 = pA[0], A1 = pA[1];
        float4 B0 = pB[0], B1 = pB[1];

        area += sum8(A0, A1) + sum8(B0, B1);
        grad += hdiff7(A0, A1) + hdiff7(B0, B1);
        if (lane < 31) {
            float nA = Bp[r0 * W + col + 8];
            float nB = Bp[(r0 + 1) * W + col + 8];
            grad += fabsf(A1.w - nA) + fabsf(B1.w - nB);
        }
        grad += vdiff8(A0, A1, B0, B1);           // row r0 -> r0+1

        if (warp < 3) {
            const float4* pC = (const float4*)(Bp + (r0 + 2) * W + col);
            grad += vdiff8(B0, B1, pC[0], pC[1]); // row r0+1 -> r0+2
        } else {
            P0 = B0; P1 = B1;                     // defer row 7 -> next row 0
        }

        mbar_arrive(sm_addr(&smem.empty_bar[bufi]));

        // Producer: issue stage s+RING into the buffer just released
        if (tid == 0 && s + RING < NSTAGES) {
            const int ls = s + RING;
            const int lb = ls % RING;
            mbar_wait(sm_addr(&smem.empty_bar[lb]),
                      (unsigned)(((ls / RING) - 1) & 1));
            unsigned fb = sm_addr(&smem.full_bar[lb]);
            const bool last = (ls == NSTAGES - 1) && (half == 0);
            mbar_expect_tx(fb, STAGE_BYTES + (last ? (unsigned)(W * 4) : 0u));
            bulk_g2s(sm_addr(smem.buf[lb]), src_base + ls * STAGE_FLOATS,
                     STAGE_BYTES, fb);
            if (last)
                bulk_g2s(sm_addr(smem.extra), src_base + NSTAGES * STAGE_FLOATS,
                         (unsigned)(W * 4), fb);
        }
    }

    // Image-boundary vdiff: row 127 -> row 128 (half 0 only; data in smem.extra,
    // completed with stage 15's full barrier which we already waited on)
    if (warp == 3 && half == 0) {
        const float4* rn = (const float4*)(smem.extra + col);
        grad += vdiff8(P0, P1, rn[0], rn[1]);
    }

    // Reductions
    #pragma unroll
    for (int off = 16; off > 0; off >>= 1) {
        area += __shfl_xor_sync(0xffffffffu, area, off);
        grad += __shfl_xor_sync(0xffffffffu, grad, off);
    }
    if (lane == 0) { smem.s_area[warp] = area; smem.s_grad[warp] = grad; }
    __syncthreads();

    if (tid == 0) {
        float ta = (smem.s_area[0] + smem.s_area[1]) + (smem.s_area[2] + smem.s_area[3]);
        float tg = (smem.s_grad[0] + smem.s_grad[1]) + (smem.s_grad[2] + smem.s_grad[3]);
        atomicAdd(out + b, ta - PENALTY * tg);
    }
}

extern "C" void kernel_launch(void* const* d_in, const int* in_sizes, int n_in,
                              void* d_out, int out_size)
{
    const float* Y   = (const float*)d_in[0];
    float*       out = (float*)d_out;
    cudaMemsetAsync(out, 0, BATCH * sizeof(float), 0);
    grad_area_kernel<<<BATCH * 2, 128>>>(Y, out);
}

// round 9
// speedup vs baseline: 1.5646x; 1.5646x over previous
#include <cuda_runtime.h>

// GradientAwareAreaUtil: per-image  sum(Y) - 0.1*(sum|vdiff| + sum|hdiff|)
// B=512, 256x256 fp32. Direct-LDG streaming, fine-grained grid:
//   grid = 2048 CTAs (quarter image each), 128 threads, warp = 16-row band,
//   lane owns cols [8l, 8l+8) as two float4. Depth-3 register row ring,
//   branch-free via next-row clamp (row 255's vdiff partner = itself -> 0).

#define H 256
#define W 256
#define R4 (W / 4)
#define BATCH 512
#define PENALTY 0.1f

__global__ void __launch_bounds__(128, 10)
grad_area_kernel(const float* __restrict__ Y, float* __restrict__ out)
{
    const int cta  = blockIdx.x;              // 0..2047
    const int b    = cta >> 2;                // image
    const int q    = cta & 3;                 // quarter
    const int warp = threadIdx.x >> 5;
    const int lane = threadIdx.x & 31;

    const int r0 = q * 64 + warp * 16;        // this warp's 16-row band

    const float4* base = (const float4*)(Y + (size_t)b * (H * W)) + 2 * lane;

    // ring[s] holds one row's 8 floats for this lane
    float4 ring[3][2];
    #pragma unroll
    for (int i = 0; i < 3; ++i) {
        const float4* p = base + (size_t)min(r0 + i, H - 1) * R4;
        ring[i][0] = p[0];
        ring[i][1] = p[1];
    }

    float area = 0.0f, grad = 0.0f;

    #pragma unroll
    for (int i = 0; i < 16; ++i) {
        const int s  = i % 3;                 // current row slot
        const int s1 = (i + 1) % 3;           // next row slot

        float4 A0 = ring[s][0], A1 = ring[s][1];        // row r0+i

        // refill slot s with row r0+i+3 (clamped); rows beyond r0+16 unneeded
        if (i + 3 <= 16) {
            const float4* p = base + (size_t)min(r0 + i + 3, H - 1) * R4;
            ring[s][0] = p[0];
            ring[s][1] = p[1];
        }

        float4 B0 = ring[s1][0], B1 = ring[s1][1];      // row r0+i+1 (clamped)

        // area
        area += ((A0.x + A0.y) + (A0.z + A0.w)) + ((A1.x + A1.y) + (A1.z + A1.w));

        // horizontal: 7 in-lane diffs + 1 cross-lane
        grad += fabsf(A0.x - A0.y) + fabsf(A0.y - A0.z) + fabsf(A0.z - A0.w)
              + fabsf(A0.w - A1.x)
              + fabsf(A1.x - A1.y) + fabsf(A1.y - A1.z) + fabsf(A1.z - A1.w);
        float nf = __shfl_down_sync(0xffffffffu, A0.x, 1);
        if (lane < 31)
            grad += fabsf(A1.w - nf);

        // vertical vs next row (0 for global last row via clamp)
        grad += fabsf(A0.x - B0.x) + fabsf(A0.y - B0.y)
              + fabsf(A0.z - B0.z) + fabsf(A0.w - B0.w)
              + fabsf(A1.x - B1.x) + fabsf(A1.y - B1.y)
              + fabsf(A1.z - B1.z) + fabsf(A1.w - B1.w);
    }

    // warp reduction
    #pragma unroll
    for (int off = 16; off > 0; off >>= 1) {
        area += __shfl_xor_sync(0xffffffffu, area, off);
        grad += __shfl_xor_sync(0xffffffffu, grad, off);
    }

    __shared__ float s_area[4];
    __shared__ float s_grad[4];
    if (lane == 0) { s_area[warp] = area; s_grad[warp] = grad; }
    __syncthreads();

    if (threadIdx.x == 0) {
        float ta = (s_area[0] + s_area[1]) + (s_area[2] + s_area[3]);
        float tg = (s_grad[0] + s_grad[1]) + (s_grad[2] + s_grad[3]);
        atomicAdd(out + b, ta - PENALTY * tg);
    }
}

extern "C" void kernel_launch(void* const* d_in, const int* in_sizes, int n_in,
                              void* d_out, int out_size)
{
    const float* Y   = (const float*)d_in[0];
    float*       out = (float*)d_out;
    cudaMemsetAsync(out, 0, BATCH * sizeof(float), 0);
    grad_area_kernel<<<BATCH * 4, 128>>>(Y, out);
}

// round 10
// speedup vs baseline: 1.5840x; 1.0123x over previous
#include <cuda_runtime.h>

// GradientAwareAreaUtil: per-image  sum(Y) - 0.1*(sum|vdiff| + sum|hdiff|)
// B=512, 256x256 fp32. Direct-LDG streaming.
//   grid = 4096 CTAs (eighth image = 32 rows each), 128 threads,
//   warp = 8-row band, lane owns cols [8l, 8l+8) as two float4.
//   Depth-3 register row ring, branch-free via next-row clamp.
//   launch_bounds(128,16) -> up to 64 warps/SM; ~2 waves of work -> the
//   work-queue back-fills the per-CTA completion spread.

#define H 256
#define W 256
#define R4 (W / 4)
#define BATCH 512
#define PENALTY 0.1f

__global__ void __launch_bounds__(128, 16)
grad_area_kernel(const float* __restrict__ Y, float* __restrict__ out)
{
    const int cta  = blockIdx.x;              // 0..4095
    const int b    = cta >> 3;                // image
    const int oct  = cta & 7;                 // eighth
    const int warp = threadIdx.x >> 5;
    const int lane = threadIdx.x & 31;

    const int r0 = oct * 32 + warp * 8;       // this warp's 8-row band

    const float4* base = (const float4*)(Y + (size_t)b * (H * W)) + 2 * lane;

    // ring[s] holds one row's 8 floats for this lane
    float4 ring[3][2];
    #pragma unroll
    for (int i = 0; i < 3; ++i) {
        const float4* p = base + (size_t)(r0 + i) * R4;   // r0+2 <= 250, no clamp needed
        ring[i][0] = p[0];
        ring[i][1] = p[1];
    }

    float area = 0.0f, grad = 0.0f;

    #pragma unroll
    for (int i = 0; i < 8; ++i) {
        const int s  = i % 3;                 // current row slot
        const int s1 = (i + 1) % 3;           // next row slot

        float4 A0 = ring[s][0], A1 = ring[s][1];          // row r0+i

        // refill slot s with row r0+i+3 (clamped at image end; the clamp only
        // fires for the very last band, making its final vdiff |x-x| = 0)
        if (i + 3 <= 8) {
            const float4* p = base + (size_t)min(r0 + i + 3, H - 1) * R4;
            ring[s][0] = p[0];
            ring[s][1] = p[1];
        }

        float4 B0 = ring[s1][0], B1 = ring[s1][1];        // row r0+i+1 (clamped)

        // area
        area += ((A0.x + A0.y) + (A0.z + A0.w)) + ((A1.x + A1.y) + (A1.z + A1.w));

        // horizontal: 7 in-lane diffs + 1 cross-lane
        grad += fabsf(A0.x - A0.y) + fabsf(A0.y - A0.z) + fabsf(A0.z - A0.w)
              + fabsf(A0.w - A1.x)
              + fabsf(A1.x - A1.y) + fabsf(A1.y - A1.z) + fabsf(A1.z - A1.w);
        float nf = __shfl_down_sync(0xffffffffu, A0.x, 1);
        if (lane < 31)
            grad += fabsf(A1.w - nf);

        // vertical vs next row (0 for global last row via clamp)
        grad += fabsf(A0.x - B0.x) + fabsf(A0.y - B0.y)
              + fabsf(A0.z - B0.z) + fabsf(A0.w - B0.w)
              + fabsf(A1.x - B1.x) + fabsf(A1.y - B1.y)
              + fabsf(A1.z - B1.z) + fabsf(A1.w - B1.w);
    }

    // warp reduction
    #pragma unroll
    for (int off = 16; off > 0; off >>= 1) {
        area += __shfl_xor_sync(0xffffffffu, area, off);
        grad += __shfl_xor_sync(0xffffffffu, grad, off);
    }

    __shared__ float s_area[4];
    __shared__ float s_grad[4];
    if (lane == 0) { s_area[warp] = area; s_grad[warp] = grad; }
    __syncthreads();

    if (threadIdx.x == 0) {
        float ta = (s_area[0] + s_area[1]) + (s_area[2] + s_area[3]);
        float tg = (s_grad[0] + s_grad[1]) + (s_grad[2] + s_grad[3]);
        atomicAdd(out + b, ta - PENALTY * tg);
    }
}

extern "C" void kernel_launch(void* const* d_in, const int* in_sizes, int n_in,
                              void* d_out, int out_size)
{
    const float* Y   = (const float*)d_in[0];
    float*       out = (float*)d_out;
    cudaMemsetAsync(out, 0, BATCH * sizeof(float), 0);
    grad_area_kernel<<<BATCH * 8, 128>>>(Y, out);
}